// round 3
// baseline (speedup 1.0000x reference)
#include <cuda_runtime.h>
#include <cstdint>

// AddRadiusEdgeIndex: pairwise squared distances + radius mask, N=8192, r=1.
// Output: [N*N] masked_dist2 (f32), then [N*N] edge_mask as 0.0/1.0 (f32).
//
// Numerics deliberately replicate the reference bit-exactly:
//   sq[i]  = x*x + y*y + z*z                (plain mul/add, no FMA contraction)
//   dot    = fma(z, z', fma(y, y', x*x))    (FMA chain, gemm-like)
//   d2     = (sq_i + sq_j) - 2*dot ;  d2 = max(d2, 0) ; mask = d2 <= 1
//
// HBM-store-bound: 512 MB written. Persistent grid (no wave transitions),
// 32x256 tiles (1 KB contiguous per row), evict-streaming stores.

#define TI 32
#define TJ 256
#define R2 1.0f

__global__ __launch_bounds__(256, 4)
void radius_edge_kernel(const float* __restrict__ pos,
                        float* __restrict__ dist_out,
                        float* __restrict__ mask_out,
                        int n, int n_tiles, int tiles_j)
{
    __shared__ float jx[TJ], jy[TJ], jz[TJ], jsq[TJ];
    __shared__ float ix[TI], iy[TI], iz[TI], isq[TI];

    const int t  = threadIdx.x;   // 256 threads
    const int tx = t & 63;        // j-quad selector
    const int ty = t >> 6;        // i stride (0..3)
    const int jj = tx * 4;

    for (int tile = blockIdx.x; tile < n_tiles; tile += gridDim.x) {
        const int j0 = (tile % tiles_j) * TJ;
        const int i0 = (tile / tiles_j) * TI;

        __syncthreads();   // protect smem from previous iteration's readers

        // Stage tiles. sq uses plain mul/add (matches jnp.sum(pos*pos)).
        {
            int j = j0 + t;       // t covers all TJ=256
            float x = pos[3 * j + 0];
            float y = pos[3 * j + 1];
            float z = pos[3 * j + 2];
            jx[t] = x; jy[t] = y; jz[t] = z;
            jsq[t] = __fadd_rn(__fadd_rn(__fmul_rn(x, x), __fmul_rn(y, y)),
                               __fmul_rn(z, z));
        }
        if (t < TI) {
            int i = i0 + t;
            float x = pos[3 * i + 0];
            float y = pos[3 * i + 1];
            float z = pos[3 * i + 2];
            ix[t] = x; iy[t] = y; iz[t] = z;
            isq[t] = __fadd_rn(__fadd_rn(__fmul_rn(x, x), __fmul_rn(y, y)),
                               __fmul_rn(z, z));
        }
        __syncthreads();

        // Pull the j-quad into registers.
        const float xj0 = jx[jj + 0], xj1 = jx[jj + 1], xj2 = jx[jj + 2], xj3 = jx[jj + 3];
        const float yj0 = jy[jj + 0], yj1 = jy[jj + 1], yj2 = jy[jj + 2], yj3 = jy[jj + 3];
        const float zj0 = jz[jj + 0], zj1 = jz[jj + 1], zj2 = jz[jj + 2], zj3 = jz[jj + 3];
        const float sj0 = jsq[jj + 0], sj1 = jsq[jj + 1], sj2 = jsq[jj + 2], sj3 = jsq[jj + 3];

        const size_t col = (size_t)(j0 + jj);

#pragma unroll
        for (int k = 0; k < TI / 4; ++k) {
            const int il = ty + k * 4;            // local i (0..31)
            const float xi = ix[il], yi = iy[il], zi = iz[il], si = isq[il];

            float d0, d1, d2v, d3;
            {
                float dt = __fmaf_rn(zi, zj0, __fmaf_rn(yi, yj0, __fmul_rn(xi, xj0)));
                d0 = __fsub_rn(__fadd_rn(si, sj0), __fadd_rn(dt, dt));
            }
            {
                float dt = __fmaf_rn(zi, zj1, __fmaf_rn(yi, yj1, __fmul_rn(xi, xj1)));
                d1 = __fsub_rn(__fadd_rn(si, sj1), __fadd_rn(dt, dt));
            }
            {
                float dt = __fmaf_rn(zi, zj2, __fmaf_rn(yi, yj2, __fmul_rn(xi, xj2)));
                d2v = __fsub_rn(__fadd_rn(si, sj2), __fadd_rn(dt, dt));
            }
            {
                float dt = __fmaf_rn(zi, zj3, __fmaf_rn(yi, yj3, __fmul_rn(xi, xj3)));
                d3 = __fsub_rn(__fadd_rn(si, sj3), __fadd_rn(dt, dt));
            }
            d0  = fmaxf(d0, 0.0f);
            d1  = fmaxf(d1, 0.0f);
            d2v = fmaxf(d2v, 0.0f);
            d3  = fmaxf(d3, 0.0f);

            const float m0 = (d0  <= R2) ? 1.0f : 0.0f;
            const float m1 = (d1  <= R2) ? 1.0f : 0.0f;
            const float m2 = (d2v <= R2) ? 1.0f : 0.0f;
            const float m3 = (d3  <= R2) ? 1.0f : 0.0f;

            float4 dist4;
            dist4.x = m0 != 0.0f ? d0  : 0.0f;
            dist4.y = m1 != 0.0f ? d1  : 0.0f;
            dist4.z = m2 != 0.0f ? d2v : 0.0f;
            dist4.w = m3 != 0.0f ? d3  : 0.0f;

            const size_t off = (size_t)(i0 + il) * (size_t)n + col;
            __stcs(reinterpret_cast<float4*>(dist_out + off), dist4);

            if (mask_out != nullptr) {
                __stcs(reinterpret_cast<float4*>(mask_out + off),
                       make_float4(m0, m1, m2, m3));
            }
        }
    }
}

extern "C" void kernel_launch(void* const* d_in, const int* in_sizes, int n_in,
                              void* d_out, int out_size)
{
    const float* pos = (const float*)d_in[0];
    const int n = in_sizes[0] / 3;           // 8192

    float* out  = (float*)d_out;
    float* dist = out;
    const long long nn = (long long)n * (long long)n;
    float* mask = ((long long)out_size >= 2 * nn) ? (out + (size_t)nn) : nullptr;

    const int tiles_j = (n + TJ - 1) / TJ;           // 32
    const int tiles_i = (n + TI - 1) / TI;           // 256
    const int n_tiles = tiles_j * tiles_i;           // 8192

    // Persistent grid: 4 CTAs/SM x 148 SMs (152 on GB300; 592 is safe either way).
    const int grid = 592;
    radius_edge_kernel<<<grid, 256>>>(pos, dist, mask, n, n_tiles, tiles_j);
}

// round 4
// speedup vs baseline: 1.1615x; 1.1615x over previous
#include <cuda_runtime.h>
#include <cstdint>

// AddRadiusEdgeIndex: pairwise squared distances + radius mask, N=8192, r=1.
// Output: [N*N] masked_dist2 (f32), then [N*N] edge_mask as 0.0/1.0 (f32).
//
// Numerics deliberately replicate the reference bit-exactly:
//   sq[i]  = x*x + y*y + z*z                (plain mul/add, no FMA contraction)
//   dot    = fma(z, z', fma(y, y', x*x))    (FMA chain, gemm-like)
//   d2     = (sq_i + sq_j) - 2*dot ;  d2 = max(d2, 0) ; mask = d2 <= 1
//
// HBM-store-bound: 512 MB written. Non-persistent grid (best measured),
// 32x256 tiles, evict-streaming stores, 6 CTAs/SM for max store MLP.

#define TI 32
#define TJ 256
#define R2 1.0f

__global__ __launch_bounds__(256, 6)
void radius_edge_kernel(const float* __restrict__ pos,
                        float* __restrict__ dist_out,
                        float* __restrict__ mask_out,
                        int n)
{
    __shared__ float jx[TJ], jy[TJ], jz[TJ], jsq[TJ];
    __shared__ float ix[TI], iy[TI], iz[TI], isq[TI];

    const int j0 = blockIdx.x * TJ;
    const int i0 = blockIdx.y * TI;
    const int t  = threadIdx.x;   // 256 threads

    // Stage tiles. sq uses plain mul/add rounding (matches jnp.sum(pos*pos)).
    {
        int j = j0 + t;           // t covers all TJ=256
        float x = pos[3 * j + 0];
        float y = pos[3 * j + 1];
        float z = pos[3 * j + 2];
        jx[t] = x; jy[t] = y; jz[t] = z;
        jsq[t] = __fadd_rn(__fadd_rn(__fmul_rn(x, x), __fmul_rn(y, y)),
                           __fmul_rn(z, z));
    }
    if (t < TI) {
        int i = i0 + t;
        float x = pos[3 * i + 0];
        float y = pos[3 * i + 1];
        float z = pos[3 * i + 2];
        ix[t] = x; iy[t] = y; iz[t] = z;
        isq[t] = __fadd_rn(__fadd_rn(__fmul_rn(x, x), __fmul_rn(y, y)),
                           __fmul_rn(z, z));
    }
    __syncthreads();

    // Thread layout: tx in [0,64) -> j-quad (4 consecutive j), ty in [0,4).
    const int tx = t & 63;
    const int ty = t >> 6;
    const int jj = tx * 4;

    // Pull the j-quad into registers once.
    const float xj0 = jx[jj + 0], xj1 = jx[jj + 1], xj2 = jx[jj + 2], xj3 = jx[jj + 3];
    const float yj0 = jy[jj + 0], yj1 = jy[jj + 1], yj2 = jy[jj + 2], yj3 = jy[jj + 3];
    const float zj0 = jz[jj + 0], zj1 = jz[jj + 1], zj2 = jz[jj + 2], zj3 = jz[jj + 3];
    const float sj0 = jsq[jj + 0], sj1 = jsq[jj + 1], sj2 = jsq[jj + 2], sj3 = jsq[jj + 3];

    // Incremental float4 row pointers: start at row (i0+ty), advance 4 rows/iter.
    const size_t base = (size_t)(i0 + ty) * (size_t)n + (size_t)(j0 + jj);
    const size_t rowstep4 = (size_t)n;            // 4 rows, in float4 units: 4*n/4 = n
    float4* __restrict__ dptr = reinterpret_cast<float4*>(dist_out + base);
    float4* __restrict__ mptr = mask_out ? reinterpret_cast<float4*>(mask_out + base)
                                         : nullptr;

#pragma unroll
    for (int k = 0; k < TI / 4; ++k) {
        const int il = ty + k * 4;            // local i (0..31)
        const float xi = ix[il], yi = iy[il], zi = iz[il], si = isq[il];

        float d0, d1, d2v, d3;
        {
            float dt = __fmaf_rn(zi, zj0, __fmaf_rn(yi, yj0, __fmul_rn(xi, xj0)));
            d0 = __fsub_rn(__fadd_rn(si, sj0), __fadd_rn(dt, dt));
        }
        {
            float dt = __fmaf_rn(zi, zj1, __fmaf_rn(yi, yj1, __fmul_rn(xi, xj1)));
            d1 = __fsub_rn(__fadd_rn(si, sj1), __fadd_rn(dt, dt));
        }
        {
            float dt = __fmaf_rn(zi, zj2, __fmaf_rn(yi, yj2, __fmul_rn(xi, xj2)));
            d2v = __fsub_rn(__fadd_rn(si, sj2), __fadd_rn(dt, dt));
        }
        {
            float dt = __fmaf_rn(zi, zj3, __fmaf_rn(yi, yj3, __fmul_rn(xi, xj3)));
            d3 = __fsub_rn(__fadd_rn(si, sj3), __fadd_rn(dt, dt));
        }
        d0  = fmaxf(d0, 0.0f);
        d1  = fmaxf(d1, 0.0f);
        d2v = fmaxf(d2v, 0.0f);
        d3  = fmaxf(d3, 0.0f);

        const float m0 = (d0  <= R2) ? 1.0f : 0.0f;
        const float m1 = (d1  <= R2) ? 1.0f : 0.0f;
        const float m2 = (d2v <= R2) ? 1.0f : 0.0f;
        const float m3 = (d3  <= R2) ? 1.0f : 0.0f;

        float4 dist4;
        dist4.x = m0 != 0.0f ? d0  : 0.0f;
        dist4.y = m1 != 0.0f ? d1  : 0.0f;
        dist4.z = m2 != 0.0f ? d2v : 0.0f;
        dist4.w = m3 != 0.0f ? d3  : 0.0f;

        __stcs(dptr, dist4);
        dptr += rowstep4;                      // +4 rows (n float4s)
        if (mptr) {
            __stcs(mptr, make_float4(m0, m1, m2, m3));
            mptr += rowstep4;
        }
    }
}

extern "C" void kernel_launch(void* const* d_in, const int* in_sizes, int n_in,
                              void* d_out, int out_size)
{
    const float* pos = (const float*)d_in[0];
    const int n = in_sizes[0] / 3;           // 8192

    float* out  = (float*)d_out;
    float* dist = out;
    const long long nn = (long long)n * (long long)n;
    float* mask = ((long long)out_size >= 2 * nn) ? (out + (size_t)nn) : nullptr;

    dim3 grid((n + TJ - 1) / TJ, (n + TI - 1) / TI);
    radius_edge_kernel<<<grid, 256>>>(pos, dist, mask, n);
}

// round 5
// speedup vs baseline: 1.1625x; 1.0008x over previous
#include <cuda_runtime.h>
#include <cstdint>

// AddRadiusEdgeIndex: pairwise squared distances + radius mask, N=8192, r=1.
// Output: [N*N] masked_dist2 (f32), then [N*N] edge_mask as 0.0/1.0 (f32).
//
// Numerics deliberately replicate the reference bit-exactly:
//   sq[i]  = x*x + y*y + z*z                (plain mul/add, no FMA contraction)
//   dot    = fma(z, z', fma(y, y', x*x))    (FMA chain, gemm-like)
//   d2     = (sq_i + sq_j) - 2*dot ;  d2 = max(d2, 0) ; mask = d2 <= 1
//
// HBM-store-bound: 512 MB written. 32x256 tiles, evict-streaming 256-bit
// stores (STG.256, sm_100a+): 1 thread = 8 consecutive j columns, so each
// warp writes a full 1KB row segment per instruction pair.

#define TI 32
#define TJ 256
#define R2 1.0f

__device__ __forceinline__ void stg256_cs(float* p,
                                          float v0, float v1, float v2, float v3,
                                          float v4, float v5, float v6, float v7)
{
    asm volatile("st.global.cs.v8.f32 [%0], {%1,%2,%3,%4,%5,%6,%7,%8};"
                 :: "l"(p), "f"(v0), "f"(v1), "f"(v2), "f"(v3),
                    "f"(v4), "f"(v5), "f"(v6), "f"(v7)
                 : "memory");
}

__global__ __launch_bounds__(256, 3)
void radius_edge_kernel(const float* __restrict__ pos,
                        float* __restrict__ dist_out,
                        float* __restrict__ mask_out,
                        int n)
{
    __shared__ float jx[TJ], jy[TJ], jz[TJ], jsq[TJ];
    __shared__ float ix[TI], iy[TI], iz[TI], isq[TI];

    const int j0 = blockIdx.x * TJ;
    const int i0 = blockIdx.y * TI;
    const int t  = threadIdx.x;   // 256 threads

    // Stage tiles. sq uses plain mul/add rounding (matches jnp.sum(pos*pos)).
    {
        int j = j0 + t;           // t covers all TJ=256
        float x = pos[3 * j + 0];
        float y = pos[3 * j + 1];
        float z = pos[3 * j + 2];
        jx[t] = x; jy[t] = y; jz[t] = z;
        jsq[t] = __fadd_rn(__fadd_rn(__fmul_rn(x, x), __fmul_rn(y, y)),
                           __fmul_rn(z, z));
    }
    if (t < TI) {
        int i = i0 + t;
        float x = pos[3 * i + 0];
        float y = pos[3 * i + 1];
        float z = pos[3 * i + 2];
        ix[t] = x; iy[t] = y; iz[t] = z;
        isq[t] = __fadd_rn(__fadd_rn(__fmul_rn(x, x), __fmul_rn(y, y)),
                           __fmul_rn(z, z));
    }
    __syncthreads();

    // Thread layout: tx in [0,32) -> 8 consecutive j, ty in [0,8) -> i stride.
    const int tx = t & 31;
    const int ty = t >> 5;
    const int jj = tx * 8;

    // Pull the j-octet into registers once.
    float xj[8], yj[8], zj[8], sj[8];
#pragma unroll
    for (int q = 0; q < 8; ++q) {
        xj[q] = jx[jj + q];
        yj[q] = jy[jj + q];
        zj[q] = jz[jj + q];
        sj[q] = jsq[jj + q];
    }

    // Row pointers: start at row (i0+ty), advance 8 rows per iteration.
    const size_t base = (size_t)(i0 + ty) * (size_t)n + (size_t)(j0 + jj);
    float* __restrict__ dptr = dist_out + base;
    float* __restrict__ mptr = mask_out ? mask_out + base : nullptr;
    const size_t rowstep = (size_t)n * 8;     // 8 rows, in floats

#pragma unroll
    for (int k = 0; k < TI / 8; ++k) {
        const int il = ty + k * 8;            // local i (0..31)
        const float xi = ix[il], yi = iy[il], zi = iz[il], si = isq[il];

        float d[8], m[8];
#pragma unroll
        for (int q = 0; q < 8; ++q) {
            float dt = __fmaf_rn(zi, zj[q], __fmaf_rn(yi, yj[q], __fmul_rn(xi, xj[q])));
            float dd = __fsub_rn(__fadd_rn(si, sj[q]), __fadd_rn(dt, dt));
            dd = fmaxf(dd, 0.0f);
            m[q] = (dd <= R2) ? 1.0f : 0.0f;
            d[q] = (m[q] != 0.0f) ? dd : 0.0f;
        }

        stg256_cs(dptr, d[0], d[1], d[2], d[3], d[4], d[5], d[6], d[7]);
        dptr += rowstep;
        if (mptr) {
            stg256_cs(mptr, m[0], m[1], m[2], m[3], m[4], m[5], m[6], m[7]);
            mptr += rowstep;
        }
    }
}

extern "C" void kernel_launch(void* const* d_in, const int* in_sizes, int n_in,
                              void* d_out, int out_size)
{
    const float* pos = (const float*)d_in[0];
    const int n = in_sizes[0] / 3;           // 8192

    float* out  = (float*)d_out;
    float* dist = out;
    const long long nn = (long long)n * (long long)n;
    float* mask = ((long long)out_size >= 2 * nn) ? (out + (size_t)nn) : nullptr;

    dim3 grid((n + TJ - 1) / TJ, (n + TI - 1) / TI);
    radius_edge_kernel<<<grid, 256>>>(pos, dist, mask, n);
}